// round 10
// baseline (speedup 1.0000x reference)
#include <cuda_runtime.h>
#include <math.h>

#define BB 64
#define TT 32
#define EE 300
#define HH 1024
#define VV 10000

#define E_PAD 320
#define NT1   ((E_PAD + HH) / 32)   // 42 k-tiles, layer 1
#define NTILE0_1 (E_PAD / 32)       // 10
#define NT2   ((HH + HH) / 32)      // 64 k-tiles, layer 2
#define NTILE0_2 (HH / 32)          // 32
#define NBLK 64                      // n-groups of 64 gate-cols (16 units x 4 gates)

#define NPAIR 4                      // ring of 4 pairs = 8 tile stages
#define A_TILE_WORDS (64 * 32)       // 2048
#define W_TILE_WORDS (64 * 32)       // 2048
#define STAGE_WORDS  (A_TILE_WORDS + W_TILE_WORDS)   // 4096 (16KB)
#define STAGE_BYTES  (STAGE_WORDS * 4)
#define SMEM_DYN     (2 * NPAIR * STAGE_BYTES)       // 131072

// ---- persistent device scratch (no allocation allowed) ----
__device__ float g_w1pre[NBLK * NT1 * W_TILE_WORDS];  // pre-swizzled tf32 L1 W
__device__ float g_w2pre[NBLK * NT2 * W_TILE_WORDS];  // pre-swizzled tf32 L2 W
__device__ float g_x1t[TT * BB * E_PAD];              // gathered tf32 embeddings
__device__ float g_h1[2][BB * HH];
__device__ float g_h2[2][BB * HH];
__device__ float g_h1t[2][BB * HH];                   // tf32 copies (MMA A)
__device__ float g_h2t[2][BB * HH];
__device__ float g_c1[BB * HH];
__device__ float g_c2[BB * HH];
__device__ float g_bc1[4 * HH];
__device__ float g_bc2[4 * HH];

__device__ __forceinline__ unsigned cvt_tf32(float x) {
    unsigned r;
    asm("cvt.rna.tf32.f32 %0, %1;" : "=r"(r) : "f"(x));
    return r;
}

__device__ __forceinline__ void cp16(unsigned dst, const void* src) {
    asm volatile("cp.async.cg.shared.global [%0], [%1], 16;"
                 :: "r"(dst), "l"(src));
}

__global__ void init_states_kernel() {
    int i = blockIdx.x * blockDim.x + threadIdx.x;
    if (i < BB * HH) {
        g_h1[0][i] = 0.f; g_h2[0][i] = 0.f;
        g_h1t[0][i] = 0.f; g_h2t[0][i] = 0.f;
        g_c1[i] = 0.f; g_c2[i] = 0.f;
    }
}

__global__ void conv_bias_kernel(const float* __restrict__ bih1, const float* __restrict__ bhh1,
                                 const float* __restrict__ bih2, const float* __restrict__ bhh2) {
    int i = blockIdx.x * blockDim.x + threadIdx.x;
    if (i < 4 * HH) {
        g_bc1[i] = bih1[i] + bhh1[i];
        g_bc2[i] = bih2[i] + bhh2[i];
    }
}

// Gather + tf32-convert the exact embeddings needed: x1t[t][b][k].
__global__ void conv_x1_kernel(const float* __restrict__ embed,
                               const int* __restrict__ questions) {
    int t = blockIdx.y;
    int idx = blockIdx.x * 256 + threadIdx.x;   // < BB*E_PAD (20480, exact)
    int b = idx / E_PAD, k = idx % E_PAD;
    int row = questions[b * TT + t];
    float v = (k < EE) ? embed[(size_t)row * EE + k] : 0.f;
    g_x1t[(size_t)t * (BB * E_PAD) + idx] = __uint_as_float(cvt_tf32(v));
}

// Pre-swizzled tf32 weight tiles, one 2048-word image per (n-group, k-tile).
// Word d in tile: n = d>>5 (col 0..63), s = (d&31)>>2, eo = d&3 holds
// k_in_tile = ((s ^ (n&7)) << 2) + eo.
// Col n: wn = n>>5, gate = (n>>3)&3, unit = nb*16 + wn*8 + (n&7).
__global__ void conv_w_kernel(float* __restrict__ dst,
                              const float* __restrict__ Wih,
                              const float* __restrict__ Whh,
                              int Kin, int Kpad, int NT) {
    int e = blockIdx.x * 256 + threadIdx.x;   // < NBLK*NT*2048 (exact)
    int d = e & 2047;
    int tile = (e >> 11) % NT;
    int nb = (e >> 11) / NT;
    int n = d >> 5, w = d & 31, s = w >> 2, eo = w & 3;
    int kt = ((s ^ (n & 7)) << 2) + eo;
    int kg = tile * 32 + kt;
    int wn = n >> 5, j = (n >> 3) & 3, g = n & 7;
    int r = j * HH + nb * 16 + wn * 8 + g;
    float v;
    if (kg < Kpad) v = (kg < Kin) ? Wih[(size_t)r * Kin + kg] : 0.f;
    else           v = Whh[(size_t)r * HH + (kg - Kpad)];
    dst[e] = __uint_as_float(cvt_tf32(v));
}

// Merged software-pipelined step. Blocks [0,64) run L2[t2], blocks [64,128)
// run L1[t1] (independent within a launch; ordered across launches).
// Per block: M=64 (all batch) x N=64 gate-cols. 512 threads = 16 warps:
// wk = warp>>3 (k-split parity), wm = (warp>>1)&3 (16 rows), wn = warp&1
// (32 cols). 8-stage cp.async ring, one __syncthreads per tile-pair,
// k-split partials reduced through smem, thread-local LSTM epilogue.
__global__ __launch_bounds__(512, 1) void lstm_merged_step(
    const int* __restrict__ qlen, int t1, int t2)
{
    extern __shared__ __align__(16) float smem_dyn[];
    __shared__ float redS[2][4][32][17];

    const int tid  = threadIdx.x;
    const int lane = tid & 31;
    const int warp = tid >> 5;

    const bool isL2 = (t2 >= 0) && (t1 < 0 || blockIdx.x < NBLK);
    const int nbidx = isL2 ? blockIdx.x
                           : ((t2 >= 0) ? blockIdx.x - NBLK : blockIdx.x);
    const int u0 = nbidx * 16;

    int t, NT, ntile0, strideA0;
    const float *Wpre, *A0, *A1, *hprev, *bc;
    float *cb, *ho, *hoT;
    if (isL2) {
        t = t2; Wpre = g_w2pre; NT = NT2; ntile0 = NTILE0_2;
        A0 = g_h1t[(t2 + 1) & 1]; strideA0 = HH;
        A1 = g_h2t[t2 & 1]; hprev = g_h2[t2 & 1]; bc = g_bc2;
        cb = g_c2; ho = g_h2[(t2 + 1) & 1]; hoT = g_h2t[(t2 + 1) & 1];
    } else {
        t = t1; Wpre = g_w1pre; NT = NT1; ntile0 = NTILE0_1;
        A0 = g_x1t + (size_t)t1 * (BB * E_PAD); strideA0 = E_PAD;
        A1 = g_h1t[t1 & 1]; hprev = g_h1[t1 & 1]; bc = g_bc1;
        cb = g_c1; ho = g_h1[(t1 + 1) & 1]; hoT = g_h1t[(t1 + 1) & 1];
    }

    const unsigned smem_base = (unsigned)__cvta_generic_to_shared(smem_dyn);

    float acc[4][4];
#pragma unroll
    for (int j = 0; j < 4; ++j)
#pragma unroll
        for (int r = 0; r < 4; ++r) acc[j][r] = 0.f;

    const int am  = tid >> 3;     // A-load row 0..63
    const int ak4 = tid & 7;
    const unsigned a_dst_off = (unsigned)((am * 8 + (ak4 ^ (am & 7))) * 16);

    auto issue_tile = [&](int tt, int stage) {
        const unsigned ab = smem_base + (unsigned)(stage * STAGE_BYTES);
        const unsigned wb = ab + A_TILE_WORDS * 4;
        // W tile: contiguous pre-swizzled image, 1 float4 per thread (512)
        const float4* wsrc = (const float4*)(Wpre + ((size_t)nbidx * NT + tt) * (size_t)W_TILE_WORDS);
        cp16(wb + (unsigned)(tid * 16), wsrc + tid);
        // A tile: 512 float4s, 1 per thread
        const float* srcA;
        if (tt < ntile0) srcA = A0 + (size_t)am * strideA0 + tt * 32 + ak4 * 4;
        else             srcA = A1 + (size_t)am * HH + (tt - ntile0) * 32 + ak4 * 4;
        cp16(ab + a_dst_off, srcA);
    };

    auto issue_pair = [&](int p) {
        int s2 = (p % NPAIR) * 2;
        issue_tile(2 * p,     s2);
        issue_tile(2 * p + 1, s2 + 1);
    };

    const int npairs = NT >> 1;   // 21 or 32

    // Prologue: NPAIR-1 pairs in flight
#pragma unroll
    for (int p = 0; p < NPAIR - 1; ++p) {
        issue_pair(p);
        asm volatile("cp.async.commit_group;");
    }

    const int g  = lane >> 2;       // 0..7
    const int th = lane & 3;        // 0..3
    const int wk = warp >> 3;       // k-split parity
    const int wm = (warp >> 1) & 3; // m-group (16 rows)
    const int wn = warp & 1;        // n-group (32 cols)
    const int mrow = wm * 16 + g;

    for (int p = 0; p < npairs; ++p) {
        asm volatile("cp.async.wait_group %0;" :: "n"(NPAIR - 2));
        __syncthreads();

        const int stage = (p % NPAIR) * 2 + wk;
        const unsigned* __restrict__ A =
            (const unsigned*)smem_dyn + stage * STAGE_WORDS;
        const unsigned* __restrict__ W = A + A_TILE_WORDS;

#pragma unroll
        for (int c = 0; c < 4; ++c) {          // k-chunk of 8
            const int xr0 = ((2 * c)     ^ g) << 2;
            const int xr1 = ((2 * c + 1) ^ g) << 2;
            unsigned a0 = A[ mrow      * 32 + xr0 + th];
            unsigned a1 = A[(mrow + 8) * 32 + xr0 + th];
            unsigned a2 = A[ mrow      * 32 + xr1 + th];
            unsigned a3 = A[(mrow + 8) * 32 + xr1 + th];
#pragma unroll
            for (int j = 0; j < 4; ++j) {      // n-subtile == gate j
                const int n = 32 * wn + 8 * j + g;
                unsigned b0 = W[n * 32 + xr0 + th];
                unsigned b1 = W[n * 32 + xr1 + th];
                asm volatile(
                    "mma.sync.aligned.m16n8k8.row.col.f32.tf32.tf32.f32 "
                    "{%0,%1,%2,%3}, {%4,%5,%6,%7}, {%8,%9}, {%0,%1,%2,%3};"
                    : "+f"(acc[j][0]), "+f"(acc[j][1]),
                      "+f"(acc[j][2]), "+f"(acc[j][3])
                    : "r"(a0), "r"(a1), "r"(a2), "r"(a3), "r"(b0), "r"(b1));
            }
        }

        int np = p + NPAIR - 1;
        if (np < npairs) issue_pair(np);
        asm volatile("cp.async.commit_group;");   // always commit (FIFO arithmetic)
    }

    // ---- K-split reduction + thread-local LSTM cell epilogue ----
    if (wk == 1) {
#pragma unroll
        for (int j = 0; j < 4; ++j)
#pragma unroll
            for (int r = 0; r < 4; ++r)
                redS[wn][wm][lane][j * 4 + r] = acc[j][r];
    }
    __syncthreads();
    if (wk == 0) {
#pragma unroll
        for (int j = 0; j < 4; ++j)
#pragma unroll
            for (int r = 0; r < 4; ++r)
                acc[j][r] += redS[wn][wm][lane][j * 4 + r];

#pragma unroll
        for (int r = 0; r < 4; ++r) {
            int b  = wm * 16 + g + ((r >> 1) << 3);
            int gu = u0 + wn * 8 + 2 * th + (r & 1);
            float gi = acc[0][r] + bc[gu];
            float gf = acc[1][r] + bc[gu + HH];
            float gg = acc[2][r] + bc[gu + 2 * HH];
            float go = acc[3][r] + bc[gu + 3 * HH];
            int idx = b * HH + gu;
            float c_old = cb[idx];
            float h_old = hprev[idx];
            float si = 1.f / (1.f + expf(-gi));
            float sf = 1.f / (1.f + expf(-gf));
            float so = 1.f / (1.f + expf(-go));
            float tg = tanhf(gg);
            float cn = sf * c_old + si * tg;
            float hn = so * tanhf(cn);
            bool active = (t < qlen[b]);
            float cw = active ? cn : c_old;
            float hw = active ? hn : h_old;
            cb[idx]  = cw;
            ho[idx]  = hw;
            hoT[idx] = __uint_as_float(cvt_tf32(hw));
        }
    }
}

// Output: E_q [B,1024,28,28] = tiled h2, then h1, h2, c1, c2 each [B,1,H].
__global__ void write_output_kernel(
    float* __restrict__ out,
    const float* __restrict__ h1,
    const float* __restrict__ h2,
    const float* __restrict__ c1,
    const float* __restrict__ c2)
{
    const unsigned n0q = (unsigned)BB * HH * 784u / 4u;
    const unsigned sq  = (unsigned)BB * HH / 4u;
    unsigned idx = blockIdx.x * blockDim.x + threadIdx.x;
    unsigned totq = n0q + 4u * sq;
    if (idx >= totq) return;
    float4* out4 = (float4*)out;
    if (idx < n0q) {
        unsigned bh = idx / 196u;
        float v = h2[bh];
        out4[idx] = make_float4(v, v, v, v);
    } else {
        unsigned r = idx - n0q;
        unsigned sec = r / sq;
        unsigned off = r % sq;
        const float* src = (sec == 0) ? h1 : (sec == 1) ? h2 : (sec == 2) ? c1 : c2;
        out4[idx] = ((const float4*)src)[off];
    }
}

extern "C" void kernel_launch(void* const* d_in, const int* in_sizes, int n_in,
                              void* d_out, int out_size) {
    const int*   questions = (const int*)d_in[0];
    const int*   qlen      = (const int*)d_in[1];
    const float* embed     = (const float*)d_in[2];
    const float* Wih1      = (const float*)d_in[3];
    const float* Whh1      = (const float*)d_in[4];
    const float* bih1      = (const float*)d_in[5];
    const float* bhh1      = (const float*)d_in[6];
    const float* Wih2      = (const float*)d_in[7];
    const float* Whh2      = (const float*)d_in[8];
    const float* bih2      = (const float*)d_in[9];
    const float* bhh2      = (const float*)d_in[10];

    void* p;
    cudaGetSymbolAddress(&p, g_h1);  float (*h1b)[BB*HH]  = (float(*)[BB*HH])p;
    cudaGetSymbolAddress(&p, g_h2);  float (*h2b)[BB*HH]  = (float(*)[BB*HH])p;
    cudaGetSymbolAddress(&p, g_c1);  float* c1p = (float*)p;
    cudaGetSymbolAddress(&p, g_c2);  float* c2p = (float*)p;
    cudaGetSymbolAddress(&p, g_w1pre); float* w1p = (float*)p;
    cudaGetSymbolAddress(&p, g_w2pre); float* w2p = (float*)p;

    cudaFuncSetAttribute(lstm_merged_step,
                         cudaFuncAttributeMaxDynamicSharedMemorySize, SMEM_DYN);

    // ---- per-replay preprocessing ----
    conv_bias_kernel<<<(4 * HH + 255) / 256, 256>>>(bih1, bhh1, bih2, bhh2);
    {
        dim3 gx(BB * E_PAD / 256, TT);
        conv_x1_kernel<<<gx, 256>>>(embed, questions);
    }
    conv_w_kernel<<<NBLK * NT1 * W_TILE_WORDS / 256, 256>>>(w1p, Wih1, Whh1, EE, E_PAD, NT1);
    conv_w_kernel<<<NBLK * NT2 * W_TILE_WORDS / 256, 256>>>(w2p, Wih2, Whh2, HH, HH, NT2);
    init_states_kernel<<<(BB * HH + 255) / 256, 256>>>();

    // ---- software-pipelined timestep chain ----
    // K_0: L1[0] alone; K_i (i=1..31): {L2[i-1], L1[i]}; K_32: L2[31] alone.
    lstm_merged_step<<<NBLK, 512, SMEM_DYN>>>(qlen, 0, -1);
    for (int i = 1; i < TT; ++i)
        lstm_merged_step<<<2 * NBLK, 512, SMEM_DYN>>>(qlen, i, i - 1);
    lstm_merged_step<<<NBLK, 512, SMEM_DYN>>>(qlen, -1, TT - 1);

    // final states live in buffer index (T % 2) == 0
    unsigned totq = (unsigned)BB * HH * 784u / 4u + (unsigned)BB * HH;
    write_output_kernel<<<(totq + 255) / 256, 256>>>(
        (float*)d_out, h1b[0], h2b[0], c1p, c2p);
}

// round 11
// speedup vs baseline: 1.1054x; 1.1054x over previous
#include <cuda_runtime.h>
#include <math.h>

#define BB 64
#define TT 32
#define EE 300
#define HH 1024
#define VV 10000

#define E_PAD 384
#define NT1 44                        // k-tiles layer 1 (384+1024)/32
#define NTILE0_1 12
#define NT2 64                        // (1024+1024)/32
#define NTILE0_2 32
#define NBLK 64                       // blocks per layer, 64 gate-cols each

#define NSTG 12                       // tile stages = 3 quads
#define IMG_TILE_WORDS 2048           // one A or W tile image (8KB)
#define STAGE_WORDS 4096              // A + W
#define STAGE_BYTES 16384
#define SMEM_DYN (NSTG * STAGE_BYTES) // 196608

// prep_all grid sections
#define PB_W1 22528                   // 64*44*2048/256
#define PB_W2 (PB_W1 + 32768)         // + 64*64*2048/256
#define PB_X  (PB_W2 + 3072)          // + 32*12*2048/256
#define PB_B  (PB_X + 16)             // + 4096/256
#define PB_END (PB_B + 1536)          // + 6*65536/256

// ---- persistent device scratch (no allocation allowed) ----
__device__ float g_w1img[NBLK * NT1 * IMG_TILE_WORDS];
__device__ float g_w2img[NBLK * NT2 * IMG_TILE_WORDS];
__device__ float g_ximg[TT * NTILE0_1 * IMG_TILE_WORDS];
__device__ float g_h1img[2][32 * IMG_TILE_WORDS];   // h as A-image (32 k-tiles)
__device__ float g_h2img[2][32 * IMG_TILE_WORDS];
__device__ float g_h1[2][BB * HH];
__device__ float g_h2[2][BB * HH];
__device__ float g_c1[BB * HH];
__device__ float g_c2[BB * HH];
__device__ float g_bc1[4 * HH];
__device__ float g_bc2[4 * HH];

__device__ __forceinline__ unsigned cvt_tf32(float x) {
    unsigned r;
    asm("cvt.rna.tf32.f32 %0, %1;" : "=r"(r) : "f"(x));
    return r;
}

__device__ __forceinline__ void cp16(unsigned dst, const void* src) {
    asm volatile("cp.async.cg.shared.global [%0], [%1], 16;"
                 :: "r"(dst), "l"(src));
}

#define LDS128(r0,r1,r2,r3,addr) \
    asm volatile("ld.shared.v4.b32 {%0,%1,%2,%3}, [%4];" \
                 : "=r"(r0),"=r"(r1),"=r"(r2),"=r"(r3) : "r"(addr))

// Image word layout, per tile (2048 words):
//   [half(2)][c(4)][lane l(32)][8]  — half = wm (A) or wn (W)
//   physical word w holds logical idx8 = w ^ (l & 4)   (anti-conflict half-swap)
//   A: idx8 = q*2+p -> value A(row = 32*half + 8q + (l>>2), k = tile*32 + c*8 + 4p + (l&3))
//   W: idx8 = j*2+p -> value W(gate j, unit = nb*16 + half*8 + (l>>2), same k)
__device__ __forceinline__ void w_img_word(float* dst, int e,
    const float* __restrict__ Wih, const float* __restrict__ Whh,
    int Kin, int Kpad, int NT)
{
    int d = e & 2047;
    int nbtile = e >> 11;
    int tile = nbtile % NT;
    int nb = nbtile / NT;
    int wn = d >> 10;
    int c = (d >> 8) & 3;
    int l = (d >> 3) & 31;
    int idx8 = (d & 7) ^ (l & 4);
    int j = idx8 >> 1, p = idx8 & 1;
    int g = l >> 2, th = l & 3;
    int r = j * HH + nb * 16 + wn * 8 + g;
    int k = tile * 32 + c * 8 + p * 4 + th;
    float v;
    if (k < Kpad) v = (k < Kin) ? Wih[(size_t)r * Kin + k] : 0.f;
    else          v = Whh[(size_t)r * HH + (k - Kpad)];
    dst[e] = __uint_as_float(cvt_tf32(v));
}

__global__ void prep_all(const float* __restrict__ embed,
                         const int* __restrict__ questions,
                         const float* __restrict__ Wih1, const float* __restrict__ Whh1,
                         const float* __restrict__ bih1, const float* __restrict__ bhh1,
                         const float* __restrict__ Wih2, const float* __restrict__ Whh2,
                         const float* __restrict__ bih2, const float* __restrict__ bhh2)
{
    int blk = blockIdx.x;
    int tid = threadIdx.x;
    if (blk < PB_W1) {
        w_img_word(g_w1img, blk * 256 + tid, Wih1, Whh1, EE, E_PAD, NT1);
    } else if (blk < PB_W2) {
        w_img_word(g_w2img, (blk - PB_W1) * 256 + tid, Wih2, Whh2, HH, HH, NT2);
    } else if (blk < PB_X) {
        int e = (blk - PB_W2) * 256 + tid;      // < 32*12*2048
        int d = e & 2047;
        int ttile = e >> 11;
        int tile = ttile % NTILE0_1;
        int t = ttile / NTILE0_1;
        int wm = d >> 10;
        int c = (d >> 8) & 3;
        int l = (d >> 3) & 31;
        int idx8 = (d & 7) ^ (l & 4);
        int q = idx8 >> 1, p = idx8 & 1;
        int g = l >> 2, th = l & 3;
        int b = wm * 32 + q * 8 + g;
        int k = tile * 32 + c * 8 + p * 4 + th;
        int row = questions[b * TT + t];
        float v = (k < EE) ? embed[(size_t)row * EE + k] : 0.f;
        g_ximg[e] = __uint_as_float(cvt_tf32(v));
    } else if (blk < PB_B) {
        int i = (blk - PB_X) * 256 + tid;       // < 4096
        g_bc1[i] = bih1[i] + bhh1[i];
        g_bc2[i] = bih2[i] + bhh2[i];
    } else {
        int i = (blk - PB_B) * 256 + tid;       // < 6*65536
        int sec = i >> 16, off = i & 65535;
        if      (sec == 0) g_h1[0][off] = 0.f;
        else if (sec == 1) g_h2[0][off] = 0.f;
        else if (sec == 2) g_c1[off] = 0.f;
        else if (sec == 3) g_c2[off] = 0.f;
        else if (sec == 4) g_h1img[0][off] = 0.f;
        else               g_h2img[0][off] = 0.f;
    }
}

// Merged software-pipelined step. Blocks [0,64) = L2[t2], [64,128) = L1[t1].
// Per block: M=64 x N=64 gate-cols. 512 threads = 16 warps:
// wk = warp&3 (4-way k-split), wm = (warp>>2)&1 (32 rows), wn = warp>>3 (32 cols).
// Warp tile 32m x 32n, operands via 4 conflict-free LDS.128 per chunk from
// fragment-packed images. 12-stage ring (3 quads), 1 sync per quad.
__global__ __launch_bounds__(512, 1) void lstm_merged_step(
    const int* __restrict__ qlen, int t1, int t2)
{
    extern __shared__ __align__(16) float sm[];
    const int tid  = threadIdx.x;
    const int lane = tid & 31;
    const int warp = tid >> 5;

    const bool isL2 = (t2 >= 0) && (t1 < 0 || blockIdx.x < NBLK);
    const int nb = isL2 ? blockIdx.x
                        : ((t2 >= 0) ? blockIdx.x - NBLK : blockIdx.x);

    int t, NT, ntile0;
    const float *Wimg, *A0img, *A1img, *hprev, *bc;
    float *cb, *ho, *hoimg;
    if (isL2) {
        t = t2; Wimg = g_w2img; NT = NT2; ntile0 = NTILE0_2;
        A0img = g_h1img[(t2 + 1) & 1];
        A1img = g_h2img[t2 & 1];
        hprev = g_h2[t2 & 1]; bc = g_bc2; cb = g_c2;
        ho = g_h2[(t2 + 1) & 1]; hoimg = g_h2img[(t2 + 1) & 1];
    } else {
        t = t1; Wimg = g_w1img; NT = NT1; ntile0 = NTILE0_1;
        A0img = g_ximg + (size_t)t1 * (NTILE0_1 * IMG_TILE_WORDS);
        A1img = g_h1img[t1 & 1];
        hprev = g_h1[t1 & 1]; bc = g_bc1; cb = g_c1;
        ho = g_h1[(t1 + 1) & 1]; hoimg = g_h1img[(t1 + 1) & 1];
    }
    const float* Wb = Wimg + (size_t)nb * NT * IMG_TILE_WORDS;

    const unsigned smb = (unsigned)__cvta_generic_to_shared(sm);

    float acc[32];
#pragma unroll
    for (int i = 0; i < 32; ++i) acc[i] = 0.f;

    auto issue_tile = [&](int tt, int stage) {
        const float* asrc = (tt < ntile0)
            ? A0img + (size_t)tt * IMG_TILE_WORDS
            : A1img + (size_t)(tt - ntile0) * IMG_TILE_WORDS;
        const float* wsrc = Wb + (size_t)tt * IMG_TILE_WORDS;
        unsigned ab = smb + (unsigned)(stage * STAGE_BYTES);
        cp16(ab + (unsigned)(tid * 16), (const float4*)asrc + tid);
        cp16(ab + 8192u + (unsigned)(tid * 16), (const float4*)wsrc + tid);
    };
    auto issue_quad = [&](int q) {
        int s = (q % 3) * 4;
        issue_tile(4 * q,     s);
        issue_tile(4 * q + 1, s + 1);
        issue_tile(4 * q + 2, s + 2);
        issue_tile(4 * q + 3, s + 3);
    };

    const int nquads = NT >> 2;   // 11 or 16

    issue_quad(0);
    asm volatile("cp.async.commit_group;");
    issue_quad(1);
    asm volatile("cp.async.commit_group;");

    const int wk = warp & 3;
    const int wm = (warp >> 2) & 1;
    const int wn = warp >> 3;
    const int g  = lane >> 2;
    const int th = lane & 3;
    const unsigned lsw = (lane & 4) ? 16u : 0u;
    const unsigned lbase = (unsigned)(lane * 32) + lsw;

    for (int q = 0; q < nquads; ++q) {
        asm volatile("cp.async.wait_group 1;");
        __syncthreads();
        if (q + 2 < nquads) issue_quad(q + 2);
        asm volatile("cp.async.commit_group;");

        const unsigned st = smb + (unsigned)((((q % 3) << 2) + wk) * STAGE_BYTES);
        const unsigned Ab = st + (unsigned)(wm * 4096) + lbase;
        const unsigned Wsb = st + 8192u + (unsigned)(wn * 4096) + lbase;

#pragma unroll
        for (int c = 0; c < 4; ++c) {
            unsigned av0, av1, av2, av3;   // logical q0p0,q0p1,q1p0,q1p1
            unsigned au0, au1, au2, au3;   // q2p0,q2p1,q3p0,q3p1
            unsigned aaddr = Ab + (unsigned)(c * 1024);
            LDS128(av0, av1, av2, av3, aaddr);
            LDS128(au0, au1, au2, au3, aaddr ^ 16u);
            unsigned waddr = Wsb + (unsigned)(c * 1024);
            unsigned b00, b01, b10, b11;   // j0p0,j0p1,j1p0,j1p1
            unsigned b20, b21, b30, b31;   // j2p0,j2p1,j3p0,j3p1
            LDS128(b00, b01, b10, b11, waddr);
            LDS128(b20, b21, b30, b31, waddr ^ 16u);

            // mb = 0 (rows 32wm + q0,q1): A frag {a0,a1,a2,a3} = {q0p0,q1p0,q0p1,q1p1}
#define MMA(accp, A0_, A1_, A2_, A3_, B0_, B1_) \
    asm volatile("mma.sync.aligned.m16n8k8.row.col.f32.tf32.tf32.f32 " \
        "{%0,%1,%2,%3}, {%4,%5,%6,%7}, {%8,%9}, {%0,%1,%2,%3};" \
        : "+f"((accp)[0]), "+f"((accp)[1]), "+f"((accp)[2]), "+f"((accp)[3]) \
        : "r"(A0_), "r"(A1_), "r"(A2_), "r"(A3_), "r"(B0_), "r"(B1_))

            MMA(&acc[0*8 + 0], av0, av2, av1, av3, b00, b01);  // j0 mb0
            MMA(&acc[1*8 + 0], av0, av2, av1, av3, b10, b11);  // j1 mb0
            MMA(&acc[2*8 + 0], av0, av2, av1, av3, b20, b21);  // j2 mb0
            MMA(&acc[3*8 + 0], av0, av2, av1, av3, b30, b31);  // j3 mb0
            MMA(&acc[0*8 + 4], au0, au2, au1, au3, b00, b01);  // j0 mb1
            MMA(&acc[1*8 + 4], au0, au2, au1, au3, b10, b11);
            MMA(&acc[2*8 + 4], au0, au2, au1, au3, b20, b21);
            MMA(&acc[3*8 + 4], au0, au2, au1, au3, b30, b31);
#undef MMA
        }
    }

    // ---- drain ring, reduce k-split partials via smem reuse ----
    asm volatile("cp.async.wait_group 0;");
    __syncthreads();

    if (wk != 0) {
        int slot = (wk - 1) * 4 + wm * 2 + wn;
        float4* dst = (float4*)(sm + slot * 1152 + lane * 36);
#pragma unroll
        for (int i = 0; i < 8; ++i)
            dst[i] = make_float4(acc[4*i], acc[4*i+1], acc[4*i+2], acc[4*i+3]);
    }
    __syncthreads();

    if (wk == 0) {
#pragma unroll
        for (int kk = 1; kk < 4; ++kk) {
            const float4* src = (const float4*)(sm + ((kk - 1) * 4 + wm * 2 + wn) * 1152 + lane * 36);
#pragma unroll
            for (int i = 0; i < 8; ++i) {
                float4 v = src[i];
                acc[4*i]   += v.x; acc[4*i+1] += v.y;
                acc[4*i+2] += v.z; acc[4*i+3] += v.w;
            }
        }

        // ---- thread-local LSTM epilogue: 8 (b,unit) pairs per lane ----
#pragma unroll
        for (int qq = 0; qq < 4; ++qq)
#pragma unroll
            for (int e = 0; e < 2; ++e) {
                int b = wm * 32 + qq * 8 + g;
                int u = nb * 16 + wn * 8 + 2 * th + e;
                int ai = qq * 2 + e;
                float gi = acc[0*8 + ai] + bc[u];
                float gf = acc[1*8 + ai] + bc[u + HH];
                float gg = acc[2*8 + ai] + bc[u + 2*HH];
                float go = acc[3*8 + ai] + bc[u + 3*HH];
                int idx = b * HH + u;
                float c_old = cb[idx];
                float h_old = hprev[idx];
                float si = 1.f / (1.f + expf(-gi));
                float sf = 1.f / (1.f + expf(-gf));
                float so = 1.f / (1.f + expf(-go));
                float tg = tanhf(gg);
                float cn = sf * c_old + si * tg;
                float hn = so * tanhf(cn);
                bool active = (t < qlen[b]);
                float cw = active ? cn : c_old;
                float hw = active ? hn : h_old;
                cb[idx] = cw;
                ho[idx] = hw;
                // scatter into next-step A-image layout
                int tu = u >> 5, k5 = u & 31;
                int ci = k5 >> 3, kk2 = k5 & 7;
                int p = kk2 >> 2, thi = kk2 & 3;
                int li = g * 4 + thi;
                int phys = (qq * 2 + p) ^ (li & 4);
                hoimg[tu * 2048 + wm * 1024 + ci * 256 + li * 8 + phys] =
                    __uint_as_float(cvt_tf32(hw));
            }
    }
}

// Output: E_q [B,1024,28,28] = tiled h2, then h1, h2, c1, c2 each [B,1,H].
__global__ void write_output_kernel(
    float* __restrict__ out,
    const float* __restrict__ h1,
    const float* __restrict__ h2,
    const float* __restrict__ c1,
    const float* __restrict__ c2)
{
    const unsigned n0q = (unsigned)BB * HH * 784u / 4u;
    const unsigned sq  = (unsigned)BB * HH / 4u;
    unsigned idx = blockIdx.x * blockDim.x + threadIdx.x;
    unsigned totq = n0q + 4u * sq;
    if (idx >= totq) return;
    float4* out4 = (float4*)out;
    if (idx < n0q) {
        unsigned bh = idx / 196u;
        float v = h2[bh];
        out4[idx] = make_float4(v, v, v, v);
    } else {
        unsigned r = idx - n0q;
        unsigned sec = r / sq;
        unsigned off = r % sq;
        const float* src = (sec == 0) ? h1 : (sec == 1) ? h2 : (sec == 2) ? c1 : c2;
        out4[idx] = ((const float4*)src)[off];
    }
}

extern "C" void kernel_launch(void* const* d_in, const int* in_sizes, int n_in,
                              void* d_out, int out_size) {
    const int*   questions = (const int*)d_in[0];
    const int*   qlen      = (const int*)d_in[1];
    const float* embed     = (const float*)d_in[2];
    const float* Wih1      = (const float*)d_in[3];
    const float* Whh1      = (const float*)d_in[4];
    const float* bih1      = (const float*)d_in[5];
    const float* bhh1      = (const float*)d_in[6];
    const float* Wih2      = (const float*)d_in[7];
    const float* Whh2      = (const float*)d_in[8];
    const float* bih2      = (const float*)d_in[9];
    const float* bhh2      = (const float*)d_in[10];

    void* p;
    cudaGetSymbolAddress(&p, g_h1); float (*h1b)[BB*HH] = (float(*)[BB*HH])p;
    cudaGetSymbolAddress(&p, g_h2); float (*h2b)[BB*HH] = (float(*)[BB*HH])p;
    cudaGetSymbolAddress(&p, g_c1); float* c1p = (float*)p;
    cudaGetSymbolAddress(&p, g_c2); float* c2p = (float*)p;

    cudaFuncSetAttribute(lstm_merged_step,
                         cudaFuncAttributeMaxDynamicSharedMemorySize, SMEM_DYN);

    // single consolidated prep launch (also shifts ncu -s 5 onto a step kernel)
    prep_all<<<PB_END, 256>>>(embed, questions, Wih1, Whh1, bih1, bhh1,
                              Wih2, Whh2, bih2, bhh2);

    // software-pipelined timestep chain:
    // K_0: L1[0]; K_i: {L2[i-1], L1[i]}; K_32: L2[31]
    lstm_merged_step<<<NBLK, 512, SMEM_DYN>>>(qlen, 0, -1);
    for (int i = 1; i < TT; ++i)
        lstm_merged_step<<<2 * NBLK, 512, SMEM_DYN>>>(qlen, i, i - 1);
    lstm_merged_step<<<NBLK, 512, SMEM_DYN>>>(qlen, -1, TT - 1);

    // final states live in buffer index (T % 2) == 0
    unsigned totq = (unsigned)BB * HH * 784u / 4u + (unsigned)BB * HH;
    write_output_kernel<<<(totq + 255) / 256, 256>>>(
        (float*)d_out, h1b[0], h2b[0], c1p, c2p);
}

// round 12
// speedup vs baseline: 1.1409x; 1.0321x over previous
#include <cuda_runtime.h>
#include <math.h>

#define BB 64
#define TT 32
#define EE 300
#define HH 1024
#define VV 10000

#define E_PAD 384
#define NT1 44                        // k-tiles layer 1 (384+1024)/32
#define NTILE0_1 12
#define NT2 64                        // (1024+1024)/32
#define NTILE0_2 32
#define NBLK 64                       // blocks per layer, 64 gate-cols each

#define IMG_TILE_WORDS 2048           // one A or W tile image (8KB)
#define STAGE_BYTES 16384             // A tile + W tile
#define HALF_RING_STAGES 6            // 3 pair-steps in flight per half
#define HALF_RING_BYTES (HALF_RING_STAGES * STAGE_BYTES)   // 98304
#define SMEM_DYN (2 * HALF_RING_BYTES)                      // 196608

// prep_all grid sections
#define PB_W1 22528                   // 64*44*2048/256
#define PB_W2 (PB_W1 + 32768)         // + 64*64*2048/256
#define PB_X  (PB_W2 + 3072)          // + 32*12*2048/256
#define PB_B  (PB_X + 16)             // + 4096/256
#define PB_END (PB_B + 1536)          // + 6*65536/256

// ---- persistent device scratch (no allocation allowed) ----
__device__ float g_w1img[NBLK * NT1 * IMG_TILE_WORDS];
__device__ float g_w2img[NBLK * NT2 * IMG_TILE_WORDS];
__device__ float g_ximg[TT * NTILE0_1 * IMG_TILE_WORDS];
__device__ float g_h1img[2][32 * IMG_TILE_WORDS];   // h as A-image (32 k-tiles)
__device__ float g_h2img[2][32 * IMG_TILE_WORDS];
__device__ float g_h1[2][BB * HH];
__device__ float g_h2[2][BB * HH];
__device__ float g_c1[BB * HH];
__device__ float g_c2[BB * HH];
__device__ float g_bc1[4 * HH];
__device__ float g_bc2[4 * HH];

__device__ __forceinline__ unsigned cvt_tf32(float x) {
    unsigned r;
    asm("cvt.rna.tf32.f32 %0, %1;" : "=r"(r) : "f"(x));
    return r;
}

__device__ __forceinline__ void cp16(unsigned dst, const void* src) {
    asm volatile("cp.async.cg.shared.global [%0], [%1], 16;"
                 :: "r"(dst), "l"(src));
}

#define LDS128(r0,r1,r2,r3,addr) \
    asm volatile("ld.shared.v4.b32 {%0,%1,%2,%3}, [%4];" \
                 : "=r"(r0),"=r"(r1),"=r"(r2),"=r"(r3) : "r"(addr))

// Image word layout, per tile (2048 words):
//   [half(2)][c(4)][lane l(32)][8]  — half = wm (A) or wn (W)
//   physical word w holds logical idx8 = w ^ (l & 4)   (anti-conflict half-swap)
//   A: idx8 = q*2+p -> A(row = 32*half + 8q + (l>>2), k = tile*32 + c*8 + 4p + (l&3))
//   W: idx8 = j*2+p -> W(gate j, unit = nb*16 + half*8 + (l>>2), same k)
__device__ __forceinline__ void w_img_word(float* dst, int e,
    const float* __restrict__ Wih, const float* __restrict__ Whh,
    int Kin, int Kpad, int NT)
{
    int d = e & 2047;
    int nbtile = e >> 11;
    int tile = nbtile % NT;
    int nb = nbtile / NT;
    int wn = d >> 10;
    int c = (d >> 8) & 3;
    int l = (d >> 3) & 31;
    int idx8 = (d & 7) ^ (l & 4);
    int j = idx8 >> 1, p = idx8 & 1;
    int g = l >> 2, th = l & 3;
    int r = j * HH + nb * 16 + wn * 8 + g;
    int k = tile * 32 + c * 8 + p * 4 + th;
    float v;
    if (k < Kpad) v = (k < Kin) ? Wih[(size_t)r * Kin + k] : 0.f;
    else          v = Whh[(size_t)r * HH + (k - Kpad)];
    dst[e] = __uint_as_float(cvt_tf32(v));
}

__global__ void prep_all(const float* __restrict__ embed,
                         const int* __restrict__ questions,
                         const float* __restrict__ Wih1, const float* __restrict__ Whh1,
                         const float* __restrict__ bih1, const float* __restrict__ bhh1,
                         const float* __restrict__ Wih2, const float* __restrict__ Whh2,
                         const float* __restrict__ bih2, const float* __restrict__ bhh2)
{
    int blk = blockIdx.x;
    int tid = threadIdx.x;
    if (blk < PB_W1) {
        w_img_word(g_w1img, blk * 256 + tid, Wih1, Whh1, EE, E_PAD, NT1);
    } else if (blk < PB_W2) {
        w_img_word(g_w2img, (blk - PB_W1) * 256 + tid, Wih2, Whh2, HH, HH, NT2);
    } else if (blk < PB_X) {
        int e = (blk - PB_W2) * 256 + tid;      // < 32*12*2048
        int d = e & 2047;
        int ttile = e >> 11;
        int tile = ttile % NTILE0_1;
        int t = ttile / NTILE0_1;
        int wm = d >> 10;
        int c = (d >> 8) & 3;
        int l = (d >> 3) & 31;
        int idx8 = (d & 7) ^ (l & 4);
        int q = idx8 >> 1, p = idx8 & 1;
        int g = l >> 2, th = l & 3;
        int b = wm * 32 + q * 8 + g;
        int k = tile * 32 + c * 8 + p * 4 + th;
        int row = questions[b * TT + t];
        float v = (k < EE) ? embed[(size_t)row * EE + k] : 0.f;
        g_ximg[e] = __uint_as_float(cvt_tf32(v));
    } else if (blk < PB_B) {
        int i = (blk - PB_X) * 256 + tid;       // < 4096
        g_bc1[i] = bih1[i] + bhh1[i];
        g_bc2[i] = bih2[i] + bhh2[i];
    } else {
        int i = (blk - PB_B) * 256 + tid;       // < 6*65536
        int sec = i >> 16, off = i & 65535;
        if      (sec == 0) g_h1[0][off] = 0.f;
        else if (sec == 1) g_h2[0][off] = 0.f;
        else if (sec == 2) g_c1[off] = 0.f;
        else if (sec == 3) g_c2[off] = 0.f;
        else if (sec == 4) g_h1img[0][off] = 0.f;
        else               g_h2img[0][off] = 0.f;
    }
}

// Merged software-pipelined step. Blocks [0,64) = L2[t2], [64,128) = L1[t1].
// Per block: M=64 x N=64 gate-cols, 512 threads split into TWO independent
// 256-thread half-blocks (own named barrier, own cp.async ring, disjoint tile
// sets: half h takes tiles 4s+2h, 4s+2h+1). Within a half: 8 warps =
// wk2(tile parity) x wm(32 rows) x wn(32 cols), warp tile 32x32, operands via
// conflict-free LDS.128 from fragment-packed images. 4-way k-partials
// (half x wk2) reduced through ring smem after drain.
__global__ __launch_bounds__(512, 1) void lstm_merged_step(
    const int* __restrict__ qlen, int t1, int t2)
{
    extern __shared__ __align__(16) float sm[];
    const int tid   = threadIdx.x;
    const int lane  = tid & 31;
    const int warp  = tid >> 5;
    const int half  = warp >> 3;      // 0 or 1
    const int w8    = warp & 7;
    const int h_tid = tid & 255;

    const bool isL2 = (t2 >= 0) && (t1 < 0 || blockIdx.x < NBLK);
    const int nb = isL2 ? blockIdx.x
                        : ((t2 >= 0) ? blockIdx.x - NBLK : blockIdx.x);

    int t, NT, ntile0;
    const float *Wimg, *A0img, *A1img, *hprev, *bc;
    float *cb, *ho, *hoimg;
    if (isL2) {
        t = t2; Wimg = g_w2img; NT = NT2; ntile0 = NTILE0_2;
        A0img = g_h1img[(t2 + 1) & 1];
        A1img = g_h2img[t2 & 1];
        hprev = g_h2[t2 & 1]; bc = g_bc2; cb = g_c2;
        ho = g_h2[(t2 + 1) & 1]; hoimg = g_h2img[(t2 + 1) & 1];
    } else {
        t = t1; Wimg = g_w1img; NT = NT1; ntile0 = NTILE0_1;
        A0img = g_ximg + (size_t)t1 * (NTILE0_1 * IMG_TILE_WORDS);
        A1img = g_h1img[t1 & 1];
        hprev = g_h1[t1 & 1]; bc = g_bc1; cb = g_c1;
        ho = g_h1[(t1 + 1) & 1]; hoimg = g_h1img[(t1 + 1) & 1];
    }
    const float* Wb = Wimg + (size_t)nb * NT * IMG_TILE_WORDS;

    const unsigned smb = (unsigned)__cvta_generic_to_shared(sm)
                       + (unsigned)(half * HALF_RING_BYTES);

    float acc[32];
#pragma unroll
    for (int i = 0; i < 32; ++i) acc[i] = 0.f;

    // issue one tile into a half-ring stage: 256 threads, 4 cp16 each
    auto issue_tile = [&](int tt, int stage) {
        const float* asrc = (tt < ntile0)
            ? A0img + (size_t)tt * IMG_TILE_WORDS
            : A1img + (size_t)(tt - ntile0) * IMG_TILE_WORDS;
        const float* wsrc = Wb + (size_t)tt * IMG_TILE_WORDS;
        unsigned ab = smb + (unsigned)(stage * STAGE_BYTES);
#pragma unroll
        for (int j = 0; j < 2; ++j) {
            int i4 = h_tid + j * 256;
            cp16(ab + (unsigned)(i4 * 16), (const float4*)asrc + i4);
            cp16(ab + 8192u + (unsigned)(i4 * 16), (const float4*)wsrc + i4);
        }
    };
    // step s for this half: tiles 4s+2h and 4s+2h+1
    auto issue_step = [&](int s) {
        int st = (s % 3) * 2;
        int tb = 4 * s + 2 * half;
        issue_tile(tb,     st);
        issue_tile(tb + 1, st + 1);
    };

    const int nsteps = NT >> 2;   // 11 or 16 per half

    issue_step(0);
    asm volatile("cp.async.commit_group;");
    issue_step(1);
    asm volatile("cp.async.commit_group;");

    const int wk2 = w8 & 1;
    const int wm  = (w8 >> 1) & 1;
    const int wn  = (w8 >> 2) & 1;
    const int g   = lane >> 2;
    const int th  = lane & 3;
    const unsigned lbase = (unsigned)(lane * 32) + ((lane & 4) ? 16u : 0u);
    const int barid = half + 1;

    for (int s = 0; s < nsteps; ++s) {
        asm volatile("cp.async.wait_group 1;");
        asm volatile("bar.sync %0, 256;" :: "r"(barid));
        if (s + 2 < nsteps) issue_step(s + 2);
        asm volatile("cp.async.commit_group;");

        const unsigned st = smb + (unsigned)(((s % 3) * 2 + wk2) * STAGE_BYTES);
        const unsigned Ab  = st + (unsigned)(wm * 4096) + lbase;
        const unsigned Wsb = st + 8192u + (unsigned)(wn * 4096) + lbase;

#pragma unroll
        for (int c = 0; c < 4; ++c) {
            unsigned av0, av1, av2, av3;   // logical q0p0,q0p1,q1p0,q1p1
            unsigned au0, au1, au2, au3;   // q2p0,q2p1,q3p0,q3p1
            unsigned aaddr = Ab + (unsigned)(c * 1024);
            LDS128(av0, av1, av2, av3, aaddr);
            LDS128(au0, au1, au2, au3, aaddr ^ 16u);
            unsigned waddr = Wsb + (unsigned)(c * 1024);
            unsigned b00, b01, b10, b11;   // j0p0,j0p1,j1p0,j1p1
            unsigned b20, b21, b30, b31;   // j2p0,j2p1,j3p0,j3p1
            LDS128(b00, b01, b10, b11, waddr);
            LDS128(b20, b21, b30, b31, waddr ^ 16u);

#define MMA(accp, A0_, A1_, A2_, A3_, B0_, B1_) \
    asm volatile("mma.sync.aligned.m16n8k8.row.col.f32.tf32.tf32.f32 " \
        "{%0,%1,%2,%3}, {%4,%5,%6,%7}, {%8,%9}, {%0,%1,%2,%3};" \
        : "+f"((accp)[0]), "+f"((accp)[1]), "+f"((accp)[2]), "+f"((accp)[3]) \
        : "r"(A0_), "r"(A1_), "r"(A2_), "r"(A3_), "r"(B0_), "r"(B1_))

            MMA(&acc[0*8 + 0], av0, av2, av1, av3, b00, b01);  // j0 mb0
            MMA(&acc[1*8 + 0], av0, av2, av1, av3, b10, b11);  // j1 mb0
            MMA(&acc[2*8 + 0], av0, av2, av1, av3, b20, b21);  // j2 mb0
            MMA(&acc[3*8 + 0], av0, av2, av1, av3, b30, b31);  // j3 mb0
            MMA(&acc[0*8 + 4], au0, au2, au1, au3, b00, b01);  // j0 mb1
            MMA(&acc[1*8 + 4], au0, au2, au1, au3, b10, b11);
            MMA(&acc[2*8 + 4], au0, au2, au1, au3, b20, b21);
            MMA(&acc[3*8 + 4], au0, au2, au1, au3, b30, b31);
#undef MMA
        }
    }

    // ---- drain both half-rings, 4-way k-reduce via smem reuse ----
    asm volatile("cp.async.wait_group 0;");
    __syncthreads();

    const int kslot = half * 2 + wk2;           // 0..3
    if (kslot != 0) {
        int slot = (kslot - 1) * 4 + wm * 2 + wn;   // 0..11
        float4* dst = (float4*)(sm + slot * 1152 + lane * 36);
#pragma unroll
        for (int i = 0; i < 8; ++i)
            dst[i] = make_float4(acc[4*i], acc[4*i+1], acc[4*i+2], acc[4*i+3]);
    }
    __syncthreads();

    if (kslot == 0) {
#pragma unroll
        for (int kk = 1; kk < 4; ++kk) {
            const float4* src = (const float4*)(sm + ((kk - 1) * 4 + wm * 2 + wn) * 1152 + lane * 36);
#pragma unroll
            for (int i = 0; i < 8; ++i) {
                float4 v = src[i];
                acc[4*i]   += v.x; acc[4*i+1] += v.y;
                acc[4*i+2] += v.z; acc[4*i+3] += v.w;
            }
        }

        // ---- thread-local LSTM epilogue: 8 (b,unit) pairs per lane ----
#pragma unroll
        for (int qq = 0; qq < 4; ++qq)
#pragma unroll
            for (int e = 0; e < 2; ++e) {
                int b = wm * 32 + qq * 8 + g;
                int u = nb * 16 + wn * 8 + 2 * th + e;
                int ai = qq * 2 + e;
                float gi = acc[0*8 + ai] + bc[u];
                float gf = acc[1*8 + ai] + bc[u + HH];
                float gg = acc[2*8 + ai] + bc[u + 2*HH];
                float go = acc[3*8 + ai] + bc[u + 3*HH];
                int idx = b * HH + u;
                float c_old = cb[idx];
                float h_old = hprev[idx];
                float si = 1.f / (1.f + expf(-gi));
                float sf = 1.f / (1.f + expf(-gf));
                float so = 1.f / (1.f + expf(-go));
                float tg = tanhf(gg);
                float cn = sf * c_old + si * tg;
                float hn = so * tanhf(cn);
                bool active = (t < qlen[b]);
                float cw = active ? cn : c_old;
                float hw = active ? hn : h_old;
                cb[idx] = cw;
                ho[idx] = hw;
                // scatter into next-step A-image layout
                int tu = u >> 5, k5 = u & 31;
                int ci = k5 >> 3, kk2 = k5 & 7;
                int p = kk2 >> 2, thi = kk2 & 3;
                int li = g * 4 + thi;
                int phys = (qq * 2 + p) ^ (li & 4);
                hoimg[tu * 2048 + wm * 1024 + ci * 256 + li * 8 + phys] =
                    __uint_as_float(cvt_tf32(hw));
            }
    }
}

// Output: E_q [B,1024,28,28] = tiled h2, then h1, h2, c1, c2 each [B,1,H].
__global__ void write_output_kernel(
    float* __restrict__ out,
    const float* __restrict__ h1,
    const float* __restrict__ h2,
    const float* __restrict__ c1,
    const float* __restrict__ c2)
{
    const unsigned n0q = (unsigned)BB * HH * 784u / 4u;
    const unsigned sq  = (unsigned)BB * HH / 4u;
    unsigned idx = blockIdx.x * blockDim.x + threadIdx.x;
    unsigned totq = n0q + 4u * sq;
    if (idx >= totq) return;
    float4* out4 = (float4*)out;
    if (idx < n0q) {
        unsigned bh = idx / 196u;
        float v = h2[bh];
        out4[idx] = make_float4(v, v, v, v);
    } else {
        unsigned r = idx - n0q;
        unsigned sec = r / sq;
        unsigned off = r % sq;
        const float* src = (sec == 0) ? h1 : (sec == 1) ? h2 : (sec == 2) ? c1 : c2;
        out4[idx] = ((const float4*)src)[off];
    }
}

extern "C" void kernel_launch(void* const* d_in, const int* in_sizes, int n_in,
                              void* d_out, int out_size) {
    const int*   questions = (const int*)d_in[0];
    const int*   qlen      = (const int*)d_in[1];
    const float* embed     = (const float*)d_in[2];
    const float* Wih1      = (const float*)d_in[3];
    const float* Whh1      = (const float*)d_in[4];
    const float* bih1      = (const float*)d_in[5];
    const float* bhh1      = (const float*)d_in[6];
    const float* Wih2      = (const float*)d_in[7];
    const float* Whh2      = (const float*)d_in[8];
    const float* bih2      = (const float*)d_in[9];
    const float* bhh2      = (const float*)d_in[10];

    void* p;
    cudaGetSymbolAddress(&p, g_h1); float (*h1b)[BB*HH] = (float(*)[BB*HH])p;
    cudaGetSymbolAddress(&p, g_h2); float (*h2b)[BB*HH] = (float(*)[BB*HH])p;
    cudaGetSymbolAddress(&p, g_c1); float* c1p = (float*)p;
    cudaGetSymbolAddress(&p, g_c2); float* c2p = (float*)p;

    cudaFuncSetAttribute(lstm_merged_step,
                         cudaFuncAttributeMaxDynamicSharedMemorySize, SMEM_DYN);

    // single consolidated prep launch
    prep_all<<<PB_END, 256>>>(embed, questions, Wih1, Whh1, bih1, bhh1,
                              Wih2, Whh2, bih2, bhh2);

    // software-pipelined timestep chain:
    // K_0: L1[0]; K_i: {L2[i-1], L1[i]}; K_32: L2[31]
    lstm_merged_step<<<NBLK, 512, SMEM_DYN>>>(qlen, 0, -1);
    for (int i = 1; i < TT; ++i)
        lstm_merged_step<<<2 * NBLK, 512, SMEM_DYN>>>(qlen, i, i - 1);
    lstm_merged_step<<<NBLK, 512, SMEM_DYN>>>(qlen, -1, TT - 1);

    // final states live in buffer index (T % 2) == 0
    unsigned totq = (unsigned)BB * HH * 784u / 4u + (unsigned)BB * HH;
    write_output_kernel<<<(totq + 255) / 256, 256>>>(
        (float*)d_out, h1b[0], h2b[0], c1p, c2p);
}

// round 13
// speedup vs baseline: 1.1662x; 1.0222x over previous
#include <cuda_runtime.h>
#include <math.h>

#define BB 64
#define TT 32
#define EE 300
#define HH 1024
#define VV 10000

#define E_PAD 384
#define NT1 44                        // k-tiles layer 1 (384+1024)/32
#define NTILE0_1 12
#define NT2 64                        // (1024+1024)/32
#define NTILE0_2 32
#define NBLK 64                       // blocks per layer, 64 gate-cols each

#define IMG_TILE_WORDS 2048           // one A or W tile image (8KB)
#define STAGE_BYTES 16384             // A tile + W tile
#define HALF_RING_STAGES 6            // 3 pair-steps in flight per half
#define HALF_RING_BYTES (HALF_RING_STAGES * STAGE_BYTES)   // 98304
#define SMEM_DYN (2 * HALF_RING_BYTES)                      // 196608

// prep_all grid sections
#define PB_W1 22528                   // 64*44*2048/256
#define PB_W2 (PB_W1 + 32768)         // + 64*64*2048/256
#define PB_X  (PB_W2 + 3072)          // + 32*12*2048/256
#define PB_B  (PB_X + 16)             // + 4096/256
#define PB_Z  (PB_B + 1536)           // + 6*65536/256
#define PB_END (PB_Z + 1)             // + counters

// ---- persistent device scratch (no allocation allowed) ----
__device__ float g_w1img[NBLK * NT1 * IMG_TILE_WORDS];
__device__ float g_w2img[NBLK * NT2 * IMG_TILE_WORDS];
__device__ float g_ximg[TT * NTILE0_1 * IMG_TILE_WORDS];
__device__ float g_h1img[2][32 * IMG_TILE_WORDS];   // h as A-image (32 k-tiles)
__device__ float g_h2img[2][32 * IMG_TILE_WORDS];
__device__ float g_h1[2][BB * HH];
__device__ float g_h2[2][BB * HH];
__device__ float g_c1[BB * HH];
__device__ float g_c2[BB * HH];
__device__ float g_bc1[4 * HH];
__device__ float g_bc2[4 * HH];
__device__ unsigned g_cnt1[TT];       // L1 phase-completion counters
__device__ unsigned g_cnt2[TT];       // L2 phase-completion counters

__device__ __forceinline__ unsigned cvt_tf32(float x) {
    unsigned r;
    asm("cvt.rna.tf32.f32 %0, %1;" : "=r"(r) : "f"(x));
    return r;
}

__device__ __forceinline__ void cp16(unsigned dst, const void* src) {
    asm volatile("cp.async.cg.shared.global [%0], [%1], 16;"
                 :: "r"(dst), "l"(src));
}

__device__ __forceinline__ unsigned ld_acq(const unsigned* p) {
    unsigned v;
    asm volatile("ld.acquire.gpu.global.b32 %0, [%1];" : "=r"(v) : "l"(p));
    return v;
}

#define LDS128(r0,r1,r2,r3,addr) \
    asm volatile("ld.shared.v4.b32 {%0,%1,%2,%3}, [%4];" \
                 : "=r"(r0),"=r"(r1),"=r"(r2),"=r"(r3) : "r"(addr))

// Image word layout, per tile (2048 words):
//   [half(2)][c(4)][lane l(32)][8]  — half = wm (A) or wn (W)
//   physical word w holds logical idx8 = w ^ (l & 4)   (anti-conflict half-swap)
//   A: idx8 = q*2+p -> A(row = 32*half + 8q + (l>>2), k = tile*32 + c*8 + 4p + (l&3))
//   W: idx8 = j*2+p -> W(gate j, unit = nb*16 + half*8 + (l>>2), same k)
__device__ __forceinline__ void w_img_word(float* dst, int e,
    const float* __restrict__ Wih, const float* __restrict__ Whh,
    int Kin, int Kpad, int NT)
{
    int d = e & 2047;
    int nbtile = e >> 11;
    int tile = nbtile % NT;
    int nb = nbtile / NT;
    int wn = d >> 10;
    int c = (d >> 8) & 3;
    int l = (d >> 3) & 31;
    int idx8 = (d & 7) ^ (l & 4);
    int j = idx8 >> 1, p = idx8 & 1;
    int g = l >> 2, th = l & 3;
    int r = j * HH + nb * 16 + wn * 8 + g;
    int k = tile * 32 + c * 8 + p * 4 + th;
    float v;
    if (k < Kpad) v = (k < Kin) ? Wih[(size_t)r * Kin + k] : 0.f;
    else          v = Whh[(size_t)r * HH + (k - Kpad)];
    dst[e] = __uint_as_float(cvt_tf32(v));
}

__global__ void prep_all(const float* __restrict__ embed,
                         const int* __restrict__ questions,
                         const float* __restrict__ Wih1, const float* __restrict__ Whh1,
                         const float* __restrict__ bih1, const float* __restrict__ bhh1,
                         const float* __restrict__ Wih2, const float* __restrict__ Whh2,
                         const float* __restrict__ bih2, const float* __restrict__ bhh2)
{
    int blk = blockIdx.x;
    int tid = threadIdx.x;
    if (blk < PB_W1) {
        w_img_word(g_w1img, blk * 256 + tid, Wih1, Whh1, EE, E_PAD, NT1);
    } else if (blk < PB_W2) {
        w_img_word(g_w2img, (blk - PB_W1) * 256 + tid, Wih2, Whh2, HH, HH, NT2);
    } else if (blk < PB_X) {
        int e = (blk - PB_W2) * 256 + tid;      // < 32*12*2048
        int d = e & 2047;
        int ttile = e >> 11;
        int tile = ttile % NTILE0_1;
        int t = ttile / NTILE0_1;
        int wm = d >> 10;
        int c = (d >> 8) & 3;
        int l = (d >> 3) & 31;
        int idx8 = (d & 7) ^ (l & 4);
        int q = idx8 >> 1, p = idx8 & 1;
        int g = l >> 2, th = l & 3;
        int b = wm * 32 + q * 8 + g;
        int k = tile * 32 + c * 8 + p * 4 + th;
        int row = questions[b * TT + t];
        float v = (k < EE) ? embed[(size_t)row * EE + k] : 0.f;
        g_ximg[e] = __uint_as_float(cvt_tf32(v));
    } else if (blk < PB_B) {
        int i = (blk - PB_X) * 256 + tid;       // < 4096
        g_bc1[i] = bih1[i] + bhh1[i];
        g_bc2[i] = bih2[i] + bhh2[i];
    } else if (blk < PB_Z) {
        int i = (blk - PB_B) * 256 + tid;       // < 6*65536
        int sec = i >> 16, off = i & 65535;
        if      (sec == 0) g_h1[0][off] = 0.f;
        else if (sec == 1) g_h2[0][off] = 0.f;
        else if (sec == 2) g_c1[off] = 0.f;
        else if (sec == 3) g_c2[off] = 0.f;
        else if (sec == 4) g_h1img[0][off] = 0.f;
        else               g_h2img[0][off] = 0.f;
    } else {
        if (tid < TT) { g_cnt1[tid] = 0u; g_cnt2[tid] = 0u; }
    }
}

// Persistent merged LSTM: 128 co-resident CTAs (1/SM).
// Blocks [0,64) = L2-role, [64,128) = L1-role; nb = blockIdx & 63.
// Each role iterates its 32 phases, synchronized by epoch counters:
//   L1 phase t: needs cnt1[t-1]=64 (h1[t-1]) and cnt2[t-2]=64 (ping-pong
//               back-pressure: L2 consumed h1img[(t+1)&1]).
//   L2 phase t: needs cnt1[t]=64 (h1[t]) and cnt2[t-1]=64 (h2[t-1]).
// Per phase, per CTA: M=64 x N=64 gate-cols GEMM + LSTM cell, two
// independent 256-thread half-blocks (named barriers, own cp.async rings,
// disjoint tile sets), fragment-packed images, 4-way k-partials reduced
// through ring smem, thread-local epilogue, h scattered into next image.
__global__ __launch_bounds__(512, 1) void lstm_persist(
    const int* __restrict__ qlen)
{
    extern __shared__ __align__(16) float sm[];
    const int tid   = threadIdx.x;
    const int lane  = tid & 31;
    const int warp  = tid >> 5;
    const int half  = warp >> 3;      // 0 or 1
    const int w8    = warp & 7;
    const int h_tid = tid & 255;

    const bool isL2 = blockIdx.x < NBLK;
    const int nb = blockIdx.x & (NBLK - 1);

    const int NT     = isL2 ? NT2 : NT1;
    const int ntile0 = isL2 ? NTILE0_2 : NTILE0_1;
    const int nsteps = NT >> 2;
    const float* Wb  = (isL2 ? g_w2img : g_w1img)
                     + (size_t)nb * NT * IMG_TILE_WORDS;
    const float* bc  = isL2 ? g_bc2 : g_bc1;
    float* cb        = isL2 ? g_c2 : g_c1;

    const unsigned smb = (unsigned)__cvta_generic_to_shared(sm)
                       + (unsigned)(half * HALF_RING_BYTES);

    const int wk2 = w8 & 1;
    const int wm  = (w8 >> 1) & 1;
    const int wn  = (w8 >> 2) & 1;
    const int g   = lane >> 2;
    const int th  = lane & 3;
    const unsigned lbase = (unsigned)(lane * 32) + ((lane & 4) ? 16u : 0u);
    const int barid = half + 1;
    const int kslot = half * 2 + wk2;

    for (int t = 0; t < TT; ++t) {
        // ---- epoch-barrier waits (decoupled groups) ----
        if (tid == 0) {
            if (isL2) {
                while (ld_acq(&g_cnt1[t]) < NBLK) __nanosleep(40);
                if (t > 0) while (ld_acq(&g_cnt2[t - 1]) < NBLK) __nanosleep(40);
            } else {
                if (t > 0)  while (ld_acq(&g_cnt1[t - 1]) < NBLK) __nanosleep(40);
                if (t >= 2) while (ld_acq(&g_cnt2[t - 2]) < NBLK) __nanosleep(40);
            }
        }
        __syncthreads();

        // ---- per-phase pointers ----
        const float *A0img, *A1img, *hprev;
        float *ho, *hoimg;
        if (isL2) {
            A0img = g_h1img[(t + 1) & 1];
            A1img = g_h2img[t & 1];
            hprev = g_h2[t & 1];
            ho    = g_h2[(t + 1) & 1];
            hoimg = g_h2img[(t + 1) & 1];
        } else {
            A0img = g_ximg + (size_t)t * (NTILE0_1 * IMG_TILE_WORDS);
            A1img = g_h1img[t & 1];
            hprev = g_h1[t & 1];
            ho    = g_h1[(t + 1) & 1];
            hoimg = g_h1img[(t + 1) & 1];
        }

        float acc[32];
#pragma unroll
        for (int i = 0; i < 32; ++i) acc[i] = 0.f;

        auto issue_tile = [&](int tt, int stage) {
            const float* asrc = (tt < ntile0)
                ? A0img + (size_t)tt * IMG_TILE_WORDS
                : A1img + (size_t)(tt - ntile0) * IMG_TILE_WORDS;
            const float* wsrc = Wb + (size_t)tt * IMG_TILE_WORDS;
            unsigned ab = smb + (unsigned)(stage * STAGE_BYTES);
#pragma unroll
            for (int j = 0; j < 2; ++j) {
                int i4 = h_tid + j * 256;
                cp16(ab + (unsigned)(i4 * 16), (const float4*)asrc + i4);
                cp16(ab + 8192u + (unsigned)(i4 * 16), (const float4*)wsrc + i4);
            }
        };
        auto issue_step = [&](int s) {
            int st = (s % 3) * 2;
            int tb = 4 * s + 2 * half;
            issue_tile(tb,     st);
            issue_tile(tb + 1, st + 1);
        };

        issue_step(0);
        asm volatile("cp.async.commit_group;");
        issue_step(1);
        asm volatile("cp.async.commit_group;");

        for (int s = 0; s < nsteps; ++s) {
            asm volatile("cp.async.wait_group 1;");
            asm volatile("bar.sync %0, 256;" :: "r"(barid));
            if (s + 2 < nsteps) issue_step(s + 2);
            asm volatile("cp.async.commit_group;");

            const unsigned st = smb + (unsigned)(((s % 3) * 2 + wk2) * STAGE_BYTES);
            const unsigned Ab  = st + (unsigned)(wm * 4096) + lbase;
            const unsigned Wsb = st + 8192u + (unsigned)(wn * 4096) + lbase;

#pragma unroll
            for (int c = 0; c < 4; ++c) {
                unsigned av0, av1, av2, av3;   // logical q0p0,q0p1,q1p0,q1p1
                unsigned au0, au1, au2, au3;   // q2p0,q2p1,q3p0,q3p1
                unsigned aaddr = Ab + (unsigned)(c * 1024);
                LDS128(av0, av1, av2, av3, aaddr);
                LDS128(au0, au1, au2, au3, aaddr ^ 16u);
                unsigned waddr = Wsb + (unsigned)(c * 1024);
                unsigned b00, b01, b10, b11;
                unsigned b20, b21, b30, b31;
                LDS128(b00, b01, b10, b11, waddr);
                LDS128(b20, b21, b30, b31, waddr ^ 16u);

#define MMA(accp, A0_, A1_, A2_, A3_, B0_, B1_) \
    asm volatile("mma.sync.aligned.m16n8k8.row.col.f32.tf32.tf32.f32 " \
        "{%0,%1,%2,%3}, {%4,%5,%6,%7}, {%8,%9}, {%0,%1,%2,%3};" \
        : "+f"((accp)[0]), "+f"((accp)[1]), "+f"((accp)[2]), "+f"((accp)[3]) \
        : "r"(A0_), "r"(A1_), "r"(A2_), "r"(A3_), "r"(B0_), "r"(B1_))

                MMA(&acc[0*8 + 0], av0, av2, av1, av3, b00, b01);  // j0 mb0
                MMA(&acc[1*8 + 0], av0, av2, av1, av3, b10, b11);  // j1 mb0
                MMA(&acc[2*8 + 0], av0, av2, av1, av3, b20, b21);  // j2 mb0
                MMA(&acc[3*8 + 0], av0, av2, av1, av3, b30, b31);  // j3 mb0
                MMA(&acc[0*8 + 4], au0, au2, au1, au3, b00, b01);  // j0 mb1
                MMA(&acc[1*8 + 4], au0, au2, au1, au3, b10, b11);
                MMA(&acc[2*8 + 4], au0, au2, au1, au3, b20, b21);
                MMA(&acc[3*8 + 4], au0, au2, au1, au3, b30, b31);
#undef MMA
            }
        }

        // ---- drain both half-rings, 4-way k-reduce via smem reuse ----
        asm volatile("cp.async.wait_group 0;");
        __syncthreads();

        if (kslot != 0) {
            int slot = (kslot - 1) * 4 + wm * 2 + wn;   // 0..11
            float4* dst = (float4*)(sm + slot * 1152 + lane * 36);
#pragma unroll
            for (int i = 0; i < 8; ++i)
                dst[i] = make_float4(acc[4*i], acc[4*i+1], acc[4*i+2], acc[4*i+3]);
        }
        __syncthreads();

        if (kslot == 0) {
#pragma unroll
            for (int kk = 1; kk < 4; ++kk) {
                const float4* src = (const float4*)(sm + ((kk - 1) * 4 + wm * 2 + wn) * 1152 + lane * 36);
#pragma unroll
                for (int i = 0; i < 8; ++i) {
                    float4 v = src[i];
                    acc[4*i]   += v.x; acc[4*i+1] += v.y;
                    acc[4*i+2] += v.z; acc[4*i+3] += v.w;
                }
            }

            // ---- thread-local LSTM epilogue: 8 (b,unit) pairs per lane ----
#pragma unroll
            for (int qq = 0; qq < 4; ++qq)
#pragma unroll
                for (int e = 0; e < 2; ++e) {
                    int b = wm * 32 + qq * 8 + g;
                    int u = nb * 16 + wn * 8 + 2 * th + e;
                    int ai = qq * 2 + e;
                    float gi = acc[0*8 + ai] + bc[u];
                    float gf = acc[1*8 + ai] + bc[u + HH];
                    float gg = acc[2*8 + ai] + bc[u + 2*HH];
                    float go = acc[3*8 + ai] + bc[u + 3*HH];
                    int idx = b * HH + u;
                    float c_old = cb[idx];
                    float h_old = hprev[idx];
                    float si = 1.f / (1.f + expf(-gi));
                    float sf = 1.f / (1.f + expf(-gf));
                    float so = 1.f / (1.f + expf(-go));
                    float tg = tanhf(gg);
                    float cn = sf * c_old + si * tg;
                    float hn = so * tanhf(cn);
                    bool active = (t < qlen[b]);
                    float cw = active ? cn : c_old;
                    float hw = active ? hn : h_old;
                    cb[idx] = cw;
                    ho[idx] = hw;
                    // scatter into next-step A-image layout
                    int tu = u >> 5, k5 = u & 31;
                    int ci = k5 >> 3, kk2 = k5 & 7;
                    int p = kk2 >> 2, thi = kk2 & 3;
                    int li = g * 4 + thi;
                    int phys = (qq * 2 + p) ^ (li & 4);
                    hoimg[tu * 2048 + wm * 1024 + ci * 256 + li * 8 + phys] =
                        __uint_as_float(cvt_tf32(hw));
                }
            __threadfence();   // publish h/c before epoch arrive
        }
        __syncthreads();       // all warps past reduction-smem reads

        if (tid == 0) {
            __threadfence();
            atomicAdd(isL2 ? &g_cnt2[t] : &g_cnt1[t], 1u);
        }
    }
}

// Output: E_q [B,1024,28,28] = tiled h2, then h1, h2, c1, c2 each [B,1,H].
__global__ void write_output_kernel(
    float* __restrict__ out,
    const float* __restrict__ h1,
    const float* __restrict__ h2,
    const float* __restrict__ c1,
    const float* __restrict__ c2)
{
    const unsigned n0q = (unsigned)BB * HH * 784u / 4u;
    const unsigned sq  = (unsigned)BB * HH / 4u;
    unsigned idx = blockIdx.x * blockDim.x + threadIdx.x;
    unsigned totq = n0q + 4u * sq;
    if (idx >= totq) return;
    float4* out4 = (float4*)out;
    if (idx < n0q) {
        unsigned bh = idx / 196u;
        float v = h2[bh];
        out4[idx] = make_float4(v, v, v, v);
    } else {
        unsigned r = idx - n0q;
        unsigned sec = r / sq;
        unsigned off = r % sq;
        const float* src = (sec == 0) ? h1 : (sec == 1) ? h2 : (sec == 2) ? c1 : c2;
        out4[idx] = ((const float4*)src)[off];
    }
}

extern "C" void kernel_launch(void* const* d_in, const int* in_sizes, int n_in,
                              void* d_out, int out_size) {
    const int*   questions = (const int*)d_in[0];
    const int*   qlen      = (const int*)d_in[1];
    const float* embed     = (const float*)d_in[2];
    const float* Wih1      = (const float*)d_in[3];
    const float* Whh1      = (const float*)d_in[4];
    const float* bih1      = (const float*)d_in[5];
    const float* bhh1      = (const float*)d_in[6];
    const float* Wih2      = (const float*)d_in[7];
    const float* Whh2      = (const float*)d_in[8];
    const float* bih2      = (const float*)d_in[9];
    const float* bhh2      = (const float*)d_in[10];

    void* p;
    cudaGetSymbolAddress(&p, g_h1); float (*h1b)[BB*HH] = (float(*)[BB*HH])p;
    cudaGetSymbolAddress(&p, g_h2); float (*h2b)[BB*HH] = (float(*)[BB*HH])p;
    cudaGetSymbolAddress(&p, g_c1); float* c1p = (float*)p;
    cudaGetSymbolAddress(&p, g_c2); float* c2p = (float*)p;

    cudaFuncSetAttribute(lstm_persist,
                         cudaFuncAttributeMaxDynamicSharedMemorySize, SMEM_DYN);

    // single consolidated prep launch (also zeroes epoch counters each replay)
    prep_all<<<PB_END, 256>>>(embed, questions, Wih1, Whh1, bih1, bhh1,
                              Wih2, Whh2, bih2, bhh2);

    // one persistent kernel runs all 64 layer-steps with internal barriers
    lstm_persist<<<2 * NBLK, 512, SMEM_DYN>>>(qlen);

    // final states live in buffer index (T % 2) == 0
    unsigned totq = (unsigned)BB * HH * 784u / 4u + (unsigned)BB * HH;
    write_output_kernel<<<(totq + 255) / 256, 256>>>(
        (float*)d_out, h1b[0], h2b[0], c1p, c2p);
}

// round 14
// speedup vs baseline: 1.8674x; 1.6013x over previous
#include <cuda_runtime.h>
#include <cuda_fp16.h>
#include <math.h>

#define BB 64
#define TT 32
#define EE 300
#define HH 1024
#define VV 10000

#define E_PAD 384
#define NT1 44                        // k-tiles layer 1 (384+1024)/32
#define NTILE0_1 12
#define NT2 64                        // (1024+1024)/32
#define NTILE0_2 32
#define NBLK 64                       // blocks per layer, 64 gate-cols each

#define IMG_TILE_WORDS 1024           // one A or W tile image (4KB, fp16x2 words)
#define STAGE_BYTES 8192              // A tile + W tile
#define HALF_RING_STAGES 8            // 4 pair-steps in flight per half
#define HALF_RING_BYTES (HALF_RING_STAGES * STAGE_BYTES)   // 65536
#define SMEM_DYN (2 * HALF_RING_BYTES)                      // 131072

// prep_all grid sections (256 threads each, exact word counts)
#define PW1 11264                     // 64*44*1024/256
#define PW2 (PW1 + 16384)             // + 64*64*1024/256
#define PX  (PW2 + 1536)              // + 32*12*1024/256
#define PBI (PX + 16)                 // + 4096/256
#define PZ  (PBI + 1280)              // + (4*65536 + 2*32768)/256
#define PEND (PZ + 1)                 // + counters

// ---- persistent device scratch (no allocation allowed) ----
__device__ unsigned g_w1img[NBLK * NT1 * IMG_TILE_WORDS];
__device__ unsigned g_w2img[NBLK * NT2 * IMG_TILE_WORDS];
__device__ unsigned g_ximg[TT * NTILE0_1 * IMG_TILE_WORDS];
__device__ unsigned g_h1img[2][32 * IMG_TILE_WORDS];   // h as A-image
__device__ unsigned g_h2img[2][32 * IMG_TILE_WORDS];
__device__ float g_h1[2][BB * HH];
__device__ float g_h2[2][BB * HH];
__device__ float g_c1[BB * HH];
__device__ float g_c2[BB * HH];
__device__ float g_bc1[4 * HH];
__device__ float g_bc2[4 * HH];
__device__ unsigned g_cnt1[TT];       // L1 phase-completion counters
__device__ unsigned g_cnt2[TT];       // L2 phase-completion counters

__device__ __forceinline__ unsigned pack_h2(float lo, float hi) {
    return (unsigned)__half_as_ushort(__float2half_rn(lo))
         | ((unsigned)__half_as_ushort(__float2half_rn(hi)) << 16);
}

__device__ __forceinline__ void cp16(unsigned dst, const void* src) {
    asm volatile("cp.async.cg.shared.global [%0], [%1], 16;"
                 :: "r"(dst), "l"(src));
}

__device__ __forceinline__ unsigned ld_acq(const unsigned* p) {
    unsigned v;
    asm volatile("ld.acquire.gpu.global.b32 %0, [%1];" : "=r"(v) : "l"(p));
    return v;
}

#define LDS128(r0,r1,r2,r3,addr) \
    asm volatile("ld.shared.v4.b32 {%0,%1,%2,%3}, [%4];" \
                 : "=r"(r0),"=r"(r1),"=r"(r2),"=r"(r3) : "r"(addr))

// fp16 image word layout, per 32-k tile (1024 fp16x2 words):
//   [half(2)][kstep(2)][lane l(32)][8]   — half = wm (A) or wn (W)
//   physical word w holds logical idx8 = w ^ (l & 4)   (anti-conflict swap)
//   A: idx8 = mb*4 + khalf*2 + rsel ->
//        A(row = 32*half + 16*mb + 8*rsel + (l>>2),
//          k pair = tile*32 + kstep*16 + khalf*8 + 2*(l&3))
//   W: idx8 = j*2 + khalf ->
//        W(gate j, unit = nb*16 + half*8 + (l>>2), same k pair)
__device__ __forceinline__ void w_img_word(unsigned* dst, int e,
    const float* __restrict__ Wih, const float* __restrict__ Whh,
    int Kin, int Kpad, int NT)
{
    int d = e & 1023;
    int nbtile = e >> 10;
    int tile = nbtile % NT;
    int nb = nbtile / NT;
    int half = d >> 9;
    int kstep = (d >> 8) & 1;
    int l = (d >> 3) & 31;
    int idx8 = (d & 7) ^ (l & 4);
    int j = idx8 >> 1, khalf = idx8 & 1;
    int g = l >> 2, th = l & 3;
    int r = j * HH + nb * 16 + half * 8 + g;
    int k = tile * 32 + kstep * 16 + khalf * 8 + 2 * th;
    float lo, hi;
    if (k < Kpad) {
        lo = (k < Kin)     ? Wih[(size_t)r * Kin + k] : 0.f;
        hi = (k + 1 < Kin) ? Wih[(size_t)r * Kin + k + 1] : 0.f;
    } else {
        lo = Whh[(size_t)r * HH + (k - Kpad)];
        hi = Whh[(size_t)r * HH + (k - Kpad) + 1];
    }
    dst[e] = pack_h2(lo, hi);
}

__global__ void prep_all(const float* __restrict__ embed,
                         const int* __restrict__ questions,
                         const float* __restrict__ Wih1, const float* __restrict__ Whh1,
                         const float* __restrict__ bih1, const float* __restrict__ bhh1,
                         const float* __restrict__ Wih2, const float* __restrict__ Whh2,
                         const float* __restrict__ bih2, const float* __restrict__ bhh2)
{
    int blk = blockIdx.x;
    int tid = threadIdx.x;
    if (blk < PW1) {
        w_img_word(g_w1img, blk * 256 + tid, Wih1, Whh1, EE, E_PAD, NT1);
    } else if (blk < PW2) {
        w_img_word(g_w2img, (blk - PW1) * 256 + tid, Wih2, Whh2, HH, HH, NT2);
    } else if (blk < PX) {
        int e = (blk - PW2) * 256 + tid;      // < 32*12*1024
        int d = e & 1023;
        int ttile = e >> 10;
        int tile = ttile % NTILE0_1;
        int t = ttile / NTILE0_1;
        int half = d >> 9;
        int kstep = (d >> 8) & 1;
        int l = (d >> 3) & 31;
        int idx8 = (d & 7) ^ (l & 4);
        int mb = idx8 >> 2, khalf = (idx8 >> 1) & 1, rsel = idx8 & 1;
        int g = l >> 2, th = l & 3;
        int b = 32 * half + 16 * mb + 8 * rsel + g;
        int k = tile * 32 + kstep * 16 + khalf * 8 + 2 * th;
        int row = questions[b * TT + t];
        float lo = (k < EE)     ? embed[(size_t)row * EE + k] : 0.f;
        float hi = (k + 1 < EE) ? embed[(size_t)row * EE + k + 1] : 0.f;
        g_ximg[e] = pack_h2(lo, hi);
    } else if (blk < PBI) {
        int i = (blk - PX) * 256 + tid;       // < 4096
        g_bc1[i] = bih1[i] + bhh1[i];
        g_bc2[i] = bih2[i] + bhh2[i];
    } else if (blk < PZ) {
        int i = (blk - PBI) * 256 + tid;      // < 4*65536 + 2*32768
        if (i < 262144) {
            int sec = i >> 16, off = i & 65535;
            if      (sec == 0) g_h1[0][off] = 0.f;
            else if (sec == 1) g_h2[0][off] = 0.f;
            else if (sec == 2) g_c1[off] = 0.f;
            else               g_c2[off] = 0.f;
        } else {
            int j = i - 262144;
            if (j < 32768) g_h1img[0][j] = 0u;
            else           g_h2img[0][j - 32768] = 0u;
        }
    } else {
        if (tid < TT) { g_cnt1[tid] = 0u; g_cnt2[tid] = 0u; }
    }
}

// Persistent merged LSTM: 128 co-resident CTAs (1/SM).
// Blocks [0,64) = L2-role, [64,128) = L1-role; nb = blockIdx & 63.
//   L1 phase t waits cnt1[t-1]=64 and cnt2[t-2]=64 (ping-pong back-pressure).
//   L2 phase t waits cnt1[t]=64 and cnt2[t-1]=64.
// Per phase per CTA: M=64 x N=64 gate-cols fp16 GEMM (m16n8k16, f32 accum)
// + LSTM cell. Two independent 256-thread half-blocks (named barriers, own
// cp.async rings, disjoint tile sets), fragment-packed fp16 images, 4-way
// k-partials reduced through ring smem, thread-local epilogue, h written to
// fp32 state + scattered into next fp16 A-image.
__global__ __launch_bounds__(512, 1) void lstm_persist(
    const int* __restrict__ qlen)
{
    extern __shared__ __align__(16) float sm[];
    const int tid   = threadIdx.x;
    const int lane  = tid & 31;
    const int warp  = tid >> 5;
    const int half  = warp >> 3;      // 0 or 1
    const int w8    = warp & 7;
    const int h_tid = tid & 255;

    const bool isL2 = blockIdx.x < NBLK;
    const int nb = blockIdx.x & (NBLK - 1);

    const int NT     = isL2 ? NT2 : NT1;
    const int ntile0 = isL2 ? NTILE0_2 : NTILE0_1;
    const int nsteps = NT >> 2;
    const unsigned* Wb = (isL2 ? g_w2img : g_w1img)
                       + (size_t)nb * NT * IMG_TILE_WORDS;
    const float* bc  = isL2 ? g_bc2 : g_bc1;
    float* cb        = isL2 ? g_c2 : g_c1;

    const unsigned smb = (unsigned)__cvta_generic_to_shared(sm)
                       + (unsigned)(half * HALF_RING_BYTES);

    const int wk2 = w8 & 1;
    const int wm  = (w8 >> 1) & 1;
    const int wn  = (w8 >> 2) & 1;
    const int g   = lane >> 2;
    const int th  = lane & 3;
    const unsigned lbase = (unsigned)(lane * 32) + ((lane & 4) ? 16u : 0u);
    const int barid = half + 1;
    const int kslot = half * 2 + wk2;

    // constant part of the h-image scatter address (see layout comment)
    const int scat_base = (nb >> 1) * 1024 + wm * 512 + (nb & 1) * 256 + lane * 8;

    for (int t = 0; t < TT; ++t) {
        // ---- epoch-barrier waits (decoupled groups) ----
        if (tid == 0) {
            if (isL2) {
                while (ld_acq(&g_cnt1[t]) < NBLK) __nanosleep(40);
                if (t > 0) while (ld_acq(&g_cnt2[t - 1]) < NBLK) __nanosleep(40);
            } else {
                if (t > 0)  while (ld_acq(&g_cnt1[t - 1]) < NBLK) __nanosleep(40);
                if (t >= 2) while (ld_acq(&g_cnt2[t - 2]) < NBLK) __nanosleep(40);
            }
        }
        __syncthreads();

        // ---- per-phase pointers ----
        const unsigned *A0img, *A1img;
        const float *hprev;
        float *ho;
        unsigned *hoimg;
        if (isL2) {
            A0img = g_h1img[(t + 1) & 1];
            A1img = g_h2img[t & 1];
            hprev = g_h2[t & 1];
            ho    = g_h2[(t + 1) & 1];
            hoimg = g_h2img[(t + 1) & 1];
        } else {
            A0img = g_ximg + (size_t)t * (NTILE0_1 * IMG_TILE_WORDS);
            A1img = g_h1img[t & 1];
            hprev = g_h1[t & 1];
            ho    = g_h1[(t + 1) & 1];
            hoimg = g_h1img[(t + 1) & 1];
        }

        float acc[32];
#pragma unroll
        for (int i = 0; i < 32; ++i) acc[i] = 0.f;

        auto issue_tile = [&](int tt, int stage) {
            const unsigned* asrc = (tt < ntile0)
                ? A0img + (size_t)tt * IMG_TILE_WORDS
                : A1img + (size_t)(tt - ntile0) * IMG_TILE_WORDS;
            const unsigned* wsrc = Wb + (size_t)tt * IMG_TILE_WORDS;
            unsigned ab = smb + (unsigned)(stage * STAGE_BYTES);
            cp16(ab + (unsigned)(h_tid * 16), (const uint4*)asrc + h_tid);
            cp16(ab + 4096u + (unsigned)(h_tid * 16), (const uint4*)wsrc + h_tid);
        };
        auto issue_step = [&](int s) {
            int st = (s & 3) * 2;
            int tb = 4 * s + 2 * half;
            issue_tile(tb,     st);
            issue_tile(tb + 1, st + 1);
        };

        issue_step(0);
        asm volatile("cp.async.commit_group;");
        issue_step(1);
        asm volatile("cp.async.commit_group;");
        issue_step(2);
        asm volatile("cp.async.commit_group;");

        for (int s = 0; s < nsteps; ++s) {
            asm volatile("cp.async.wait_group 2;");
            asm volatile("bar.sync %0, 256;" :: "r"(barid));
            if (s + 3 < nsteps) issue_step(s + 3);
            asm volatile("cp.async.commit_group;");

            const unsigned st = smb + (unsigned)((((s & 3) << 1) + wk2) * STAGE_BYTES);
            const unsigned Ab  = st + (unsigned)(wm * 2048) + lbase;
            const unsigned Wsb = st + 4096u + (unsigned)(wn * 2048) + lbase;

#pragma unroll
            for (int c = 0; c < 2; ++c) {      // kstep of 16
                unsigned x0,x1,x2,x3,x4,x5,x6,x7;   // A logical idx8 0..7
                unsigned w0,w1,w2,w3,w4,w5,w6,w7;   // W logical idx8 0..7
                unsigned aaddr = Ab + (unsigned)(c * 1024);
                LDS128(x0, x1, x2, x3, aaddr);
                LDS128(x4, x5, x6, x7, aaddr ^ 16u);
                unsigned waddr = Wsb + (unsigned)(c * 1024);
                LDS128(w0, w1, w2, w3, waddr);
                LDS128(w4, w5, w6, w7, waddr ^ 16u);

#define MMAH(accp, A0_, A1_, A2_, A3_, B0_, B1_) \
    asm volatile("mma.sync.aligned.m16n8k16.row.col.f32.f16.f16.f32 " \
        "{%0,%1,%2,%3}, {%4,%5,%6,%7}, {%8,%9}, {%0,%1,%2,%3};" \
        : "+f"((accp)[0]), "+f"((accp)[1]), "+f"((accp)[2]), "+f"((accp)[3]) \
        : "r"(A0_), "r"(A1_), "r"(A2_), "r"(A3_), "r"(B0_), "r"(B1_))

                MMAH(&acc[0*8 + 0], x0, x1, x2, x3, w0, w1);  // j0 mb0
                MMAH(&acc[1*8 + 0], x0, x1, x2, x3, w2, w3);  // j1 mb0
                MMAH(&acc[2*8 + 0], x0, x1, x2, x3, w4, w5);  // j2 mb0
                MMAH(&acc[3*8 + 0], x0, x1, x2, x3, w6, w7);  // j3 mb0
                MMAH(&acc[0*8 + 4], x4, x5, x6, x7, w0, w1);  // j0 mb1
                MMAH(&acc[1*8 + 4], x4, x5, x6, x7, w2, w3);
                MMAH(&acc[2*8 + 4], x4, x5, x6, x7, w4, w5);
                MMAH(&acc[3*8 + 4], x4, x5, x6, x7, w6, w7);
#undef MMAH
            }
        }

        // ---- drain both half-rings, 4-way k-reduce via smem reuse ----
        asm volatile("cp.async.wait_group 0;");
        __syncthreads();

        if (kslot != 0) {
            int slot = (kslot - 1) * 4 + wm * 2 + wn;   // 0..11
            float4* dst = (float4*)(sm + slot * 1152 + lane * 36);
#pragma unroll
            for (int i = 0; i < 8; ++i)
                dst[i] = make_float4(acc[4*i], acc[4*i+1], acc[4*i+2], acc[4*i+3]);
        }
        __syncthreads();

        if (kslot == 0) {
#pragma unroll
            for (int kk = 1; kk < 4; ++kk) {
                const float4* src = (const float4*)(sm + ((kk - 1) * 4 + wm * 2 + wn) * 1152 + lane * 36);
#pragma unroll
                for (int i = 0; i < 8; ++i) {
                    float4 v = src[i];
                    acc[4*i]   += v.x; acc[4*i+1] += v.y;
                    acc[4*i+2] += v.z; acc[4*i+3] += v.w;
                }
            }

            // ---- thread-local LSTM epilogue ----
            // acc[j*8 + mb*4 + rsel*2 + e]:
            //   b = wm*32 + mb*16 + rsel*8 + g, u = nb*16 + wn*8 + 2*th + e
#pragma unroll
            for (int mb = 0; mb < 2; ++mb)
#pragma unroll
                for (int rsel = 0; rsel < 2; ++rsel) {
                    int b = wm * 32 + mb * 16 + rsel * 8 + g;
                    bool active = (t < qlen[b]);
                    float hw2[2];
#pragma unroll
                    for (int e = 0; e < 2; ++e) {
                        int u = nb * 16 + wn * 8 + 2 * th + e;
                        int ai = mb * 4 + rsel * 2 + e;
                        float gi = acc[0*8 + ai] + bc[u];
                        float gf = acc[1*8 + ai] + bc[u + HH];
                        float gg = acc[2*8 + ai] + bc[u + 2*HH];
                        float go = acc[3*8 + ai] + bc[u + 3*HH];
                        int idx = b * HH + u;
                        float c_old = cb[idx];
                        float h_old = hprev[idx];
                        float si = 1.f / (1.f + expf(-gi));
                        float sf = 1.f / (1.f + expf(-gf));
                        float so = 1.f / (1.f + expf(-go));
                        float tg = tanhf(gg);
                        float cn = sf * c_old + si * tg;
                        float hn = so * tanhf(cn);
                        float cw = active ? cn : c_old;
                        float hw = active ? hn : h_old;
                        cb[idx] = cw;
                        ho[idx] = hw;
                        hw2[e] = hw;
                    }
                    // one fp16x2 word into next-step A-image
                    int phys = (mb * 4 + wn * 2 + rsel) ^ (lane & 4);
                    hoimg[scat_base + phys] = pack_h2(hw2[0], hw2[1]);
                }
            __threadfence();   // publish h/c before epoch arrive
        }
        __syncthreads();       // all warps past reduction-smem reads

        if (tid == 0) {
            __threadfence();
            atomicAdd(isL2 ? &g_cnt2[t] : &g_cnt1[t], 1u);
        }
    }
}

// Output: E_q [B,1024,28,28] = tiled h2, then h1, h2, c1, c2 each [B,1,H].
__global__ void write_output_kernel(
    float* __restrict__ out,
    const float* __restrict__ h1,
    const float* __restrict__ h2,
    const float* __restrict__ c1,
    const float* __restrict__ c2)
{
    const unsigned n0q = (unsigned)BB * HH * 784u / 4u;
    const unsigned sq  = (unsigned)BB * HH / 4u;
    unsigned idx = blockIdx.x * blockDim.x + threadIdx.x;
    unsigned totq = n0q + 4u * sq;
    if (idx >= totq) return;
    float4* out4 = (float4*)out;
    if (idx < n0q) {
        unsigned bh = idx / 196u;
        float v = h2[bh];
        out4[idx] = make_float4(v, v, v, v);
    } else {
        unsigned r = idx - n0q;
        unsigned sec = r / sq;
        unsigned off = r % sq;
        const float* src = (sec == 0) ? h1 : (sec == 1) ? h2 : (sec == 2) ? c1 : c2;
        out4[idx] = ((const float4*)src)[off];
    }
}

extern "C" void kernel_launch(void* const* d_in, const int* in_sizes, int n_in,
                              void* d_out, int out_size) {
    const int*   questions = (const int*)d_in[0];
    const int*   qlen      = (const int*)d_in[1];
    const float* embed     = (const float*)d_in[2];
    const float* Wih1      = (const float*)d_in[3];
    const float* Whh1      = (const float*)d_in[4];
    const float* bih1      = (const float*)d_in[5];
    const float* bhh1      = (const float*)d_in[6];
    const float* Wih2      = (const float*)d_in[7];
    const float* Whh2      = (const float*)d_in[8];
    const float* bih2      = (const float*)d_in[9];
    const float* bhh2      = (const float*)d_in[10];

    void* p;
    cudaGetSymbolAddress(&p, g_h1); float (*h1b)[BB*HH] = (float(*)[BB*HH])p;
    cudaGetSymbolAddress(&p, g_h2); float (*h2b)[BB*HH] = (float(*)[BB*HH])p;
    cudaGetSymbolAddress(&p, g_c1); float* c1p = (float*)p;
    cudaGetSymbolAddress(&p, g_c2); float* c2p = (float*)p;

    cudaFuncSetAttribute(lstm_persist,
                         cudaFuncAttributeMaxDynamicSharedMemorySize, SMEM_DYN);

    // single consolidated prep launch (also zeroes epoch counters each replay)
    prep_all<<<PEND, 256>>>(embed, questions, Wih1, Whh1, bih1, bhh1,
                            Wih2, Whh2, bih2, bhh2);

    // one persistent kernel runs all 64 layer-steps with internal barriers
    lstm_persist<<<2 * NBLK, 512, SMEM_DYN>>>(qlen);

    // final states live in buffer index (T % 2) == 0
    unsigned totq = (unsigned)BB * HH * 784u / 4u + (unsigned)BB * HH;
    write_output_kernel<<<(totq + 255) / 256, 256>>>(
        (float*)d_out, h1b[0], h2b[0], c1p, c2p);
}